// round 1
// baseline (speedup 1.0000x reference)
#include <cuda_runtime.h>
#include <math.h>

// Problem constants
#define BATCH 4096
#define TT    15
#define EMBD  300
#define HID   512
#define G3    1536          // 3*HID
#define DD    1024          // 2*HID
#define BT    (BATCH*TT)    // 61440

// ---------------- scratch (static __device__ arrays; no allocation) --------
__device__ float g_gi_f[BT * G3];        // 377 MB  input-gate preactivations fwd
__device__ float g_gi_b[BT * G3];        // 377 MB  bwd
__device__ float g_gh_f[BATCH * G3];     // 25 MB
__device__ float g_gh_b[BATCH * G3];
__device__ float g_h_f [BATCH * HID];    // 8 MB
__device__ float g_h_b [BATCH * HID];
__device__ float g_yword[BT * DD];       // 251 MB  [B,T,2H]
__device__ float g_ypool[BATCH * DD];    // 16 MB
__device__ float g_gw   [BATCH * DD];    // 16 MB   tanh(g_emb)*w_common
__device__ float g_wraw [BT];            // attention logits

// ---------------- generic NT SGEMM: C[M,N] = A[M,K] @ W[N,K]^T + bias ------
// 64x64 tile, BK=16, 256 threads, 4x4 microtile, optional row gather on A,
// optional epilogue: epi==1 -> C = tanh(acc+bias)*wc
__global__ void __launch_bounds__(256) sgemm_nt(
    const float* __restrict__ A, int lda,
    const int*   __restrict__ gather,
    const float* __restrict__ W,
    const float* __restrict__ bias,
    const float* __restrict__ wc,
    float* __restrict__ C,
    int M, int N, int K, int epi)
{
    __shared__ float As[16][64];
    __shared__ float Bs[16][64];
    const int tid = threadIdx.x;
    const int tx  = tid & 15, ty = tid >> 4;
    const int row0 = blockIdx.x * 64;
    const int col0 = blockIdx.y * 64;
    const int am = tid >> 2;       // 0..63 tile row/col for loading
    const int kq = tid & 3;        // float4 slot along K

    long arow;
    if (gather) arow = (long)gather[row0 + am] * lda;
    else        arow = (long)(row0 + am) * lda;
    const long brow = (long)(col0 + am) * K;

    float acc[4][4];
    #pragma unroll
    for (int i = 0; i < 4; i++)
        #pragma unroll
        for (int j = 0; j < 4; j++) acc[i][j] = 0.f;

    for (int k0 = 0; k0 < K; k0 += 16) {
        const int k = k0 + kq * 4;
        float4 a4, b4;
        if (k + 3 < K) {
            a4 = *(const float4*)(A + arow + k);
            b4 = *(const float4*)(W + brow + k);
        } else {
            float at[4], bt[4];
            #pragma unroll
            for (int s = 0; s < 4; s++) {
                at[s] = (k + s < K) ? A[arow + k + s] : 0.f;
                bt[s] = (k + s < K) ? W[brow + k + s] : 0.f;
            }
            a4 = make_float4(at[0], at[1], at[2], at[3]);
            b4 = make_float4(bt[0], bt[1], bt[2], bt[3]);
        }
        As[kq*4+0][am] = a4.x; As[kq*4+1][am] = a4.y;
        As[kq*4+2][am] = a4.z; As[kq*4+3][am] = a4.w;
        Bs[kq*4+0][am] = b4.x; Bs[kq*4+1][am] = b4.y;
        Bs[kq*4+2][am] = b4.z; Bs[kq*4+3][am] = b4.w;
        __syncthreads();
        #pragma unroll
        for (int kk = 0; kk < 16; kk++) {
            const float4 av = *(const float4*)&As[kk][ty * 4];
            const float4 bv = *(const float4*)&Bs[kk][tx * 4];
            acc[0][0] += av.x*bv.x; acc[0][1] += av.x*bv.y; acc[0][2] += av.x*bv.z; acc[0][3] += av.x*bv.w;
            acc[1][0] += av.y*bv.x; acc[1][1] += av.y*bv.y; acc[1][2] += av.y*bv.z; acc[1][3] += av.y*bv.w;
            acc[2][0] += av.z*bv.x; acc[2][1] += av.z*bv.y; acc[2][2] += av.z*bv.z; acc[2][3] += av.z*bv.w;
            acc[3][0] += av.w*bv.x; acc[3][1] += av.w*bv.y; acc[3][2] += av.w*bv.z; acc[3][3] += av.w*bv.w;
        }
        __syncthreads();
    }
    #pragma unroll
    for (int i = 0; i < 4; i++) {
        const int r = row0 + ty * 4 + i;
        #pragma unroll
        for (int j = 0; j < 4; j++) {
            const int n = col0 + tx * 4 + j;
            float v = acc[i][j] + bias[n];
            if (epi == 1) v = tanhf(v) * wc[n];
            C[(long)r * N + n] = v;
        }
    }
}

// ---------------- zero hidden states ---------------------------------------
__global__ void zero_h(float* __restrict__ h_f, float* __restrict__ h_b)
{
    const int i = blockIdx.x * 256 + threadIdx.x;
    h_f[i] = 0.f;
    h_b[i] = 0.f;
}

// ---------------- GRU gate update (both directions in one launch) ----------
__global__ void gru_step(const float* __restrict__ gi_f, const float* __restrict__ gi_b,
                         const float* __restrict__ gh_f, const float* __restrict__ gh_b,
                         float* __restrict__ h_f, float* __restrict__ h_b,
                         float* __restrict__ y_word, int t)
{
    const int idx = blockIdx.x * 256 + threadIdx.x;   // [0, 2*B*HID)
    const int dir = idx >= BATCH * HID;
    const int e   = dir ? idx - BATCH * HID : idx;
    const int b   = e >> 9;
    const int h   = e & (HID - 1);

    const float* gi; const float* gh; float* hbuf; int tt; int off;
    if (!dir) { gi = gi_f; gh = gh_f; hbuf = h_f; tt = t;          off = 0;   }
    else      { gi = gi_b; gh = gh_b; hbuf = h_b; tt = TT - 1 - t; off = HID; }

    const long gib = (long)(b * TT + tt) * G3;
    const long ghb = (long)b * G3;
    const float hp = hbuf[e];
    const float ir = gi[gib + h],           hr = gh[ghb + h];
    const float iz = gi[gib + HID + h],     hz = gh[ghb + HID + h];
    const float in = gi[gib + 2*HID + h],   hn = gh[ghb + 2*HID + h];
    const float r = 1.f / (1.f + expf(-(ir + hr)));
    const float z = 1.f / (1.f + expf(-(iz + hz)));
    const float n = tanhf(in + r * hn);
    const float hnew = (1.f - z) * n + z * hp;
    hbuf[e] = hnew;
    y_word[(long)(b * TT + tt) * DD + off + h] = hnew;
}

// ---------------- masked max pool over valid tokens ------------------------
__global__ void maxpool(const int* __restrict__ inds,
                        const float* __restrict__ y_word,
                        float* __restrict__ y_pool)
{
    const int idx = blockIdx.x * 256 + threadIdx.x;   // B*DD
    const int b = idx >> 10;
    const int d = idx & (DD - 1);
    float m = -INFINITY;
    #pragma unroll
    for (int t = 0; t < TT; t++) {
        if (inds[b * TT + t] != 0) {
            m = fmaxf(m, y_word[(long)(b * TT + t) * DD + d]);
        }
    }
    y_pool[idx] = m;
}

// ---------------- fused l_emb GEMM + tanh + dot with gw -> logits ----------
// w_raw[r] = sum_n tanh( y_word[r,:]@w_local[n,:] + b_local[n] ) * gw[b(r),n] + b_common
__global__ void __launch_bounds__(256) attn_weights(
    const float* __restrict__ y_word, const float* __restrict__ w_local,
    const float* __restrict__ b_local, const float* __restrict__ gw,
    const float* __restrict__ b_common, float* __restrict__ w_raw)
{
    __shared__ float As[16][64];
    __shared__ float Bs[16][64];
    __shared__ float red[64][17];
    const int tid = threadIdx.x;
    const int tx = tid & 15, ty = tid >> 4;
    const int row0 = blockIdx.x * 64;
    const int am = tid >> 2;
    const int kq = tid & 3;
    const long arow = (long)(row0 + am) * DD;

    float rowsum[4] = {0.f, 0.f, 0.f, 0.f};
    int bb[4];
    #pragma unroll
    for (int i = 0; i < 4; i++) bb[i] = (row0 + ty * 4 + i) / TT;

    for (int nt = 0; nt < DD / 64; nt++) {
        const int col0 = nt * 64;
        const long brow = (long)(col0 + am) * DD;
        float acc[4][4];
        #pragma unroll
        for (int i = 0; i < 4; i++)
            #pragma unroll
            for (int j = 0; j < 4; j++) acc[i][j] = 0.f;

        for (int k0 = 0; k0 < DD; k0 += 16) {
            const int k = k0 + kq * 4;
            const float4 a4 = *(const float4*)(y_word + arow + k);
            const float4 b4 = *(const float4*)(w_local + brow + k);
            As[kq*4+0][am] = a4.x; As[kq*4+1][am] = a4.y;
            As[kq*4+2][am] = a4.z; As[kq*4+3][am] = a4.w;
            Bs[kq*4+0][am] = b4.x; Bs[kq*4+1][am] = b4.y;
            Bs[kq*4+2][am] = b4.z; Bs[kq*4+3][am] = b4.w;
            __syncthreads();
            #pragma unroll
            for (int kk = 0; kk < 16; kk++) {
                const float4 av = *(const float4*)&As[kk][ty * 4];
                const float4 bv = *(const float4*)&Bs[kk][tx * 4];
                acc[0][0] += av.x*bv.x; acc[0][1] += av.x*bv.y; acc[0][2] += av.x*bv.z; acc[0][3] += av.x*bv.w;
                acc[1][0] += av.y*bv.x; acc[1][1] += av.y*bv.y; acc[1][2] += av.y*bv.z; acc[1][3] += av.y*bv.w;
                acc[2][0] += av.z*bv.x; acc[2][1] += av.z*bv.y; acc[2][2] += av.z*bv.z; acc[2][3] += av.z*bv.w;
                acc[3][0] += av.w*bv.x; acc[3][1] += av.w*bv.y; acc[3][2] += av.w*bv.z; acc[3][3] += av.w*bv.w;
            }
            __syncthreads();
        }
        #pragma unroll
        for (int i = 0; i < 4; i++) {
            #pragma unroll
            for (int j = 0; j < 4; j++) {
                const int n = col0 + tx * 4 + j;
                rowsum[i] += tanhf(acc[i][j] + b_local[n]) * gw[(long)bb[i] * DD + n];
            }
        }
    }
    #pragma unroll
    for (int i = 0; i < 4; i++) red[ty * 4 + i][tx] = rowsum[i];
    __syncthreads();
    if (tid < 64) {
        float s = 0.f;
        #pragma unroll
        for (int x = 0; x < 16; x++) s += red[tid][x];
        w_raw[row0 + tid] = s + b_common[0];
    }
}

// ---------------- softmax over T + weighted sum -> output ------------------
__global__ void softmax_out(const float* __restrict__ w_raw,
                            const float* __restrict__ y_word,
                            float* __restrict__ out)
{
    __shared__ float p[TT];
    const int b = blockIdx.x;
    if (threadIdx.x == 0) {
        float v[TT]; float mx = -INFINITY;
        #pragma unroll
        for (int t = 0; t < TT; t++) { v[t] = w_raw[b * TT + t]; mx = fmaxf(mx, v[t]); }
        float s = 0.f;
        #pragma unroll
        for (int t = 0; t < TT; t++) { v[t] = expf(v[t] - mx); s += v[t]; }
        const float inv = 1.f / s;
        #pragma unroll
        for (int t = 0; t < TT; t++) p[t] = v[t] * inv;
    }
    __syncthreads();
    for (int d = threadIdx.x; d < DD; d += 256) {
        float s = 0.f;
        #pragma unroll
        for (int t = 0; t < TT; t++)
            s += p[t] * y_word[((long)(b * TT + t)) * DD + d];
        out[(long)b * DD + d] = s;
    }
}

// ---------------- host launch ----------------------------------------------
extern "C" void kernel_launch(void* const* d_in, const int* in_sizes, int n_in,
                              void* d_out, int out_size)
{
    const int*   inds     = (const int*)  d_in[0];
    const float* emb      = (const float*)d_in[1];
    const float* w_ih_f   = (const float*)d_in[2];
    const float* w_hh_f   = (const float*)d_in[3];
    const float* b_ih_f   = (const float*)d_in[4];
    const float* b_hh_f   = (const float*)d_in[5];
    const float* w_ih_b   = (const float*)d_in[6];
    const float* w_hh_b   = (const float*)d_in[7];
    const float* b_ih_b   = (const float*)d_in[8];
    const float* b_hh_b   = (const float*)d_in[9];
    const float* w_local  = (const float*)d_in[10];
    const float* b_local  = (const float*)d_in[11];
    const float* w_global = (const float*)d_in[12];
    const float* b_global = (const float*)d_in[13];
    const float* w_common = (const float*)d_in[14];
    const float* b_common = (const float*)d_in[15];
    float* out = (float*)d_out;

    float *gi_f, *gi_b, *gh_f, *gh_b, *h_f, *h_b, *yw, *yp, *gw, *wraw;
    cudaGetSymbolAddress((void**)&gi_f, g_gi_f);
    cudaGetSymbolAddress((void**)&gi_b, g_gi_b);
    cudaGetSymbolAddress((void**)&gh_f, g_gh_f);
    cudaGetSymbolAddress((void**)&gh_b, g_gh_b);
    cudaGetSymbolAddress((void**)&h_f,  g_h_f);
    cudaGetSymbolAddress((void**)&h_b,  g_h_b);
    cudaGetSymbolAddress((void**)&yw,   g_yword);
    cudaGetSymbolAddress((void**)&yp,   g_ypool);
    cudaGetSymbolAddress((void**)&gw,   g_gw);
    cudaGetSymbolAddress((void**)&wraw, g_wraw);

    // 1. zero hidden states
    zero_h<<<(BATCH * HID) / 256, 256>>>(h_f, h_b);

    // 2. input-gate preactivations (embedding gather fused into A load)
    dim3 gA(BT / 64, G3 / 64);
    sgemm_nt<<<gA, 256>>>(emb, EMBD, inds, w_ih_f, b_ih_f, nullptr, gi_f, BT, G3, EMBD, 0);
    sgemm_nt<<<gA, 256>>>(emb, EMBD, inds, w_ih_b, b_ih_b, nullptr, gi_b, BT, G3, EMBD, 0);

    // 3. bidirectional GRU recurrence
    dim3 gH(BATCH / 64, G3 / 64);
    for (int t = 0; t < TT; t++) {
        sgemm_nt<<<gH, 256>>>(h_f, HID, nullptr, w_hh_f, b_hh_f, nullptr, gh_f, BATCH, G3, HID, 0);
        sgemm_nt<<<gH, 256>>>(h_b, HID, nullptr, w_hh_b, b_hh_b, nullptr, gh_b, BATCH, G3, HID, 0);
        gru_step<<<(2 * BATCH * HID) / 256, 256>>>(gi_f, gi_b, gh_f, gh_b, h_f, h_b, yw, t);
    }

    // 4. masked max pool
    maxpool<<<(BATCH * DD) / 256, 256>>>(inds, yw, yp);

    // 5. g_emb GEMM with fused tanh * w_common epilogue
    dim3 gG(BATCH / 64, DD / 64);
    sgemm_nt<<<gG, 256>>>(yp, DD, nullptr, w_global, b_global, w_common, gw, BATCH, DD, DD, 1);

    // 6. fused l_emb GEMM -> tanh -> dot(gw) -> logits
    attn_weights<<<BT / 64, 256>>>(yw, w_local, b_local, gw, b_common, wraw);

    // 7. softmax over T + weighted sum
    softmax_out<<<BATCH, 256>>>(wraw, yw, out);
}

// round 2
// speedup vs baseline: 3.0642x; 3.0642x over previous
#include <cuda_runtime.h>
#include <math.h>
#include <stdint.h>

#define BATCH 4096
#define TT    15
#define EMBD  300
#define HID   512
#define G3    1536
#define DD    1024
#define BT    (BATCH*TT)

// ---------------- scratch (static __device__ arrays) ------------------------
__device__ float g_gi_f[(size_t)BT * G3];
__device__ float g_gi_b[(size_t)BT * G3];
__device__ float g_gh_f[BATCH * G3];
__device__ float g_gh_b[BATCH * G3];
__device__ float g_h_f [BATCH * HID];
__device__ float g_h_b [BATCH * HID];
__device__ float g_yword[(size_t)BT * DD];
__device__ float g_ypool[BATCH * DD];
__device__ float g_gw  [BATCH * DD];
__device__ float g_wraw[BT];

// ---------------- TF32 helpers ----------------------------------------------
__device__ __forceinline__ uint32_t f2tf(float x) {
    uint32_t r; asm("cvt.rna.tf32.f32 %0, %1;" : "=r"(r) : "f"(x)); return r;
}
__device__ __forceinline__ void mma8(float* c,
    uint32_t a0, uint32_t a1, uint32_t a2, uint32_t a3,
    uint32_t b0, uint32_t b1)
{
    asm volatile(
        "mma.sync.aligned.m16n8k8.row.col.f32.tf32.tf32.f32 "
        "{%0,%1,%2,%3},{%4,%5,%6,%7},{%8,%9},{%0,%1,%2,%3};"
        : "+f"(c[0]), "+f"(c[1]), "+f"(c[2]), "+f"(c[3])
        : "r"(a0), "r"(a1), "r"(a2), "r"(a3), "r"(b0), "r"(b1));
}

#define SROW 36   // smem row stride in floats (32 + 4 pad; 9 float4)

// ---------------- TF32 tensor-core NT GEMM ----------------------------------
// C[M,N] = A[M,K] @ W[N,K]^T + bias
// optional row gather on A; dual param sets selected by blockIdx.z
// epi: 0 = plain, 1 = tanh(.)*wc, 2 = tanh(.)
__global__ void __launch_bounds__(256) tgemm(
    const float* __restrict__ A,  const float* __restrict__ A2, int lda,
    const int*   __restrict__ gather,
    const float* __restrict__ W,  const float* __restrict__ W2,
    const float* __restrict__ bias, const float* __restrict__ bias2,
    const float* __restrict__ wc,
    float* __restrict__ C, float* __restrict__ C2,
    int M, int N, int K, int epi)
{
    if (blockIdx.z == 1) { A = A2; W = W2; bias = bias2; C = C2; }

    __shared__ uint32_t As[128 * SROW];
    __shared__ uint32_t Bs[128 * SROW];

    const int tid  = threadIdx.x;
    const int lane = tid & 31, wid = tid >> 5;
    const int g = lane >> 2, q = lane & 3;
    const int wm0 = (wid & 3) * 32;
    const int wn0 = (wid >> 2) * 64;
    const int row0 = blockIdx.x * 128;
    const int col0 = blockIdx.y * 128;

    // gmem tile loader mapping: thread handles 4 float4 of A and 4 of B
    const int lr  = tid >> 3;   // 0..31 ; actual row = lr + i*32
    const int lc4 = tid & 7;    // float4 slot along K
    const float* aptr[4];
    const float* wptr[4];
    #pragma unroll
    for (int i = 0; i < 4; i++) {
        const int r = lr + i * 32;
        const long ra = gather ? (long)gather[row0 + r] : (long)(row0 + r);
        aptr[i] = A + ra * (long)lda;
        wptr[i] = W + (long)(col0 + r) * (long)K;
    }

    float c[2][8][4];
    #pragma unroll
    for (int mt = 0; mt < 2; mt++)
        #pragma unroll
        for (int nt = 0; nt < 8; nt++)
            #pragma unroll
            for (int j = 0; j < 4; j++) c[mt][nt][j] = 0.f;

    float4 ra[4], rb[4];
    const float4 z4 = make_float4(0.f, 0.f, 0.f, 0.f);

    // initial prefetch (k0 = 0)
    {
        const int k = lc4 * 4;
        const bool v = (k < K);
        #pragma unroll
        for (int i = 0; i < 4; i++) {
            ra[i] = v ? *(const float4*)(aptr[i] + k) : z4;
            rb[i] = v ? *(const float4*)(wptr[i] + k) : z4;
        }
    }

    const int nk = (K + 31) / 32;
    for (int it = 0; it < nk; it++) {
        __syncthreads();
        // store with permutation p(c) = (c%4)*8 + c/4  ->  p = j*8 + lc4
        #pragma unroll
        for (int i = 0; i < 4; i++) {
            const int base = (lr + i * 32) * SROW + lc4;
            As[base +  0] = f2tf(ra[i].x);
            As[base +  8] = f2tf(ra[i].y);
            As[base + 16] = f2tf(ra[i].z);
            As[base + 24] = f2tf(ra[i].w);
            Bs[base +  0] = f2tf(rb[i].x);
            Bs[base +  8] = f2tf(rb[i].y);
            Bs[base + 16] = f2tf(rb[i].z);
            Bs[base + 24] = f2tf(rb[i].w);
        }
        __syncthreads();

        if (it + 1 < nk) {
            const int k = (it + 1) * 32 + lc4 * 4;
            const bool v = (k < K);
            #pragma unroll
            for (int i = 0; i < 4; i++) {
                ra[i] = v ? *(const float4*)(aptr[i] + k) : z4;
                rb[i] = v ? *(const float4*)(wptr[i] + k) : z4;
            }
        }

        const uint4* As4 = (const uint4*)As;   // row stride 9 uint4
        const uint4* Bs4 = (const uint4*)Bs;
        #pragma unroll
        for (int h = 0; h < 2; h++) {          // two k16 halves of BK=32
            const int fo = q * 2 + h;
            const uint4 aL0 = As4[(wm0 + g     ) * 9 + fo];
            const uint4 aH0 = As4[(wm0 + g +  8) * 9 + fo];
            const uint4 aL1 = As4[(wm0 + g + 16) * 9 + fo];
            const uint4 aH1 = As4[(wm0 + g + 24) * 9 + fo];
            uint4 bf[8];
            #pragma unroll
            for (int nt = 0; nt < 8; nt++)
                bf[nt] = Bs4[(wn0 + nt * 8 + g) * 9 + fo];
            #pragma unroll
            for (int s = 0; s < 2; s++) {      // two k8 steps per half
                const uint32_t A00 = s ? aL0.z : aL0.x;
                const uint32_t A20 = s ? aL0.w : aL0.y;
                const uint32_t A10 = s ? aH0.z : aH0.x;
                const uint32_t A30 = s ? aH0.w : aH0.y;
                const uint32_t A01 = s ? aL1.z : aL1.x;
                const uint32_t A21 = s ? aL1.w : aL1.y;
                const uint32_t A11 = s ? aH1.z : aH1.x;
                const uint32_t A31 = s ? aH1.w : aH1.y;
                #pragma unroll
                for (int nt = 0; nt < 8; nt++) {
                    const uint32_t B0 = s ? bf[nt].z : bf[nt].x;
                    const uint32_t B1 = s ? bf[nt].w : bf[nt].y;
                    mma8(c[0][nt], A00, A10, A20, A30, B0, B1);
                    mma8(c[1][nt], A01, A11, A21, A31, B0, B1);
                }
            }
        }
    }

    // epilogue
    #pragma unroll
    for (int mt = 0; mt < 2; mt++) {
        const int r = row0 + wm0 + mt * 16 + g;
        #pragma unroll
        for (int nt = 0; nt < 8; nt++) {
            const int n = col0 + wn0 + nt * 8 + q * 2;
            const float b0 = bias[n], b1 = bias[n + 1];
            float v00 = c[mt][nt][0] + b0, v01 = c[mt][nt][1] + b1;
            float v10 = c[mt][nt][2] + b0, v11 = c[mt][nt][3] + b1;
            if (epi >= 1) {
                v00 = tanhf(v00); v01 = tanhf(v01);
                v10 = tanhf(v10); v11 = tanhf(v11);
                if (epi == 1) {
                    const float w0 = wc[n], w1 = wc[n + 1];
                    v00 *= w0; v01 *= w1; v10 *= w0; v11 *= w1;
                }
            }
            *(float2*)(C + (long)r * N + n)       = make_float2(v00, v01);
            *(float2*)(C + (long)(r + 8) * N + n) = make_float2(v10, v11);
        }
    }
}

// ---------------- zero hidden states ----------------------------------------
__global__ void zero_h(float* __restrict__ h_f, float* __restrict__ h_b)
{
    const int i = blockIdx.x * 256 + threadIdx.x;
    h_f[i] = 0.f;
    h_b[i] = 0.f;
}

// ---------------- GRU gate update (both directions) -------------------------
__global__ void gru_step(const float* __restrict__ gi_f, const float* __restrict__ gi_b,
                         const float* __restrict__ gh_f, const float* __restrict__ gh_b,
                         float* __restrict__ h_f, float* __restrict__ h_b,
                         float* __restrict__ y_word, int t)
{
    const int idx = blockIdx.x * 256 + threadIdx.x;
    const int dir = idx >= BATCH * HID;
    const int e   = dir ? idx - BATCH * HID : idx;
    const int b   = e >> 9;
    const int h   = e & (HID - 1);

    const float* gi; const float* gh; float* hbuf; int tt; int off;
    if (!dir) { gi = gi_f; gh = gh_f; hbuf = h_f; tt = t;          off = 0;   }
    else      { gi = gi_b; gh = gh_b; hbuf = h_b; tt = TT - 1 - t; off = HID; }

    const long gib = (long)(b * TT + tt) * G3;
    const long ghb = (long)b * G3;
    const float hp = hbuf[e];
    const float ir = gi[gib + h],         hr = gh[ghb + h];
    const float iz = gi[gib + HID + h],   hz = gh[ghb + HID + h];
    const float in = gi[gib + 2*HID + h], hn = gh[ghb + 2*HID + h];
    const float r = 1.f / (1.f + expf(-(ir + hr)));
    const float z = 1.f / (1.f + expf(-(iz + hz)));
    const float n = tanhf(in + r * hn);
    const float hnew = (1.f - z) * n + z * hp;
    hbuf[e] = hnew;
    y_word[(long)(b * TT + tt) * DD + off + h] = hnew;
}

// ---------------- masked max pool -------------------------------------------
__global__ void maxpool(const int* __restrict__ inds,
                        const float* __restrict__ y_word,
                        float* __restrict__ y_pool)
{
    const int idx = blockIdx.x * 256 + threadIdx.x;
    const int b = idx >> 10;
    const int d = idx & (DD - 1);
    float m = -INFINITY;
    #pragma unroll
    for (int t = 0; t < TT; t++) {
        if (inds[b * TT + t] != 0)
            m = fmaxf(m, y_word[(long)(b * TT + t) * DD + d]);
    }
    y_pool[idx] = m;
}

// ---------------- attention logits: w_raw[r] = <lemb[r,:], gw[b,:]> + bc ----
__global__ void __launch_bounds__(256) attn_reduce(
    const float* __restrict__ lemb, const float* __restrict__ gw,
    const float* __restrict__ b_common, float* __restrict__ wraw)
{
    const int r = blockIdx.x * 8 + (threadIdx.x >> 5);
    const int lane = threadIdx.x & 31;
    const float4* L = (const float4*)(lemb + (long)r * DD);
    const float4* G = (const float4*)(gw   + (long)(r / TT) * DD);
    float s = 0.f;
    #pragma unroll
    for (int k = 0; k < 8; k++) {
        const float4 a = L[lane + k * 32];
        const float4 b = G[lane + k * 32];
        s += a.x * b.x + a.y * b.y + a.z * b.z + a.w * b.w;
    }
    #pragma unroll
    for (int o = 16; o; o >>= 1) s += __shfl_xor_sync(0xffffffffu, s, o);
    if (lane == 0) wraw[r] = s + b_common[0];
}

// ---------------- softmax over T + weighted sum -> output -------------------
__global__ void softmax_out(const float* __restrict__ w_raw,
                            const float* __restrict__ y_word,
                            float* __restrict__ out)
{
    __shared__ float p[TT];
    const int b = blockIdx.x;
    if (threadIdx.x == 0) {
        float v[TT]; float mx = -INFINITY;
        #pragma unroll
        for (int t = 0; t < TT; t++) { v[t] = w_raw[b * TT + t]; mx = fmaxf(mx, v[t]); }
        float s = 0.f;
        #pragma unroll
        for (int t = 0; t < TT; t++) { v[t] = expf(v[t] - mx); s += v[t]; }
        const float inv = 1.f / s;
        #pragma unroll
        for (int t = 0; t < TT; t++) p[t] = v[t] * inv;
    }
    __syncthreads();
    for (int d = threadIdx.x; d < DD; d += 256) {
        float s = 0.f;
        #pragma unroll
        for (int t = 0; t < TT; t++)
            s += p[t] * y_word[((long)(b * TT + t)) * DD + d];
        out[(long)b * DD + d] = s;
    }
}

// ---------------- host launch ------------------------------------------------
extern "C" void kernel_launch(void* const* d_in, const int* in_sizes, int n_in,
                              void* d_out, int out_size)
{
    const int*   inds     = (const int*)  d_in[0];
    const float* emb      = (const float*)d_in[1];
    const float* w_ih_f   = (const float*)d_in[2];
    const float* w_hh_f   = (const float*)d_in[3];
    const float* b_ih_f   = (const float*)d_in[4];
    const float* b_hh_f   = (const float*)d_in[5];
    const float* w_ih_b   = (const float*)d_in[6];
    const float* w_hh_b   = (const float*)d_in[7];
    const float* b_ih_b   = (const float*)d_in[8];
    const float* b_hh_b   = (const float*)d_in[9];
    const float* w_local  = (const float*)d_in[10];
    const float* b_local  = (const float*)d_in[11];
    const float* w_global = (const float*)d_in[12];
    const float* b_global = (const float*)d_in[13];
    const float* w_common = (const float*)d_in[14];
    const float* b_common = (const float*)d_in[15];
    float* out = (float*)d_out;

    float *gi_f, *gi_b, *gh_f, *gh_b, *h_f, *h_b, *yw, *yp, *gw, *wraw;
    cudaGetSymbolAddress((void**)&gi_f, g_gi_f);
    cudaGetSymbolAddress((void**)&gi_b, g_gi_b);
    cudaGetSymbolAddress((void**)&gh_f, g_gh_f);
    cudaGetSymbolAddress((void**)&gh_b, g_gh_b);
    cudaGetSymbolAddress((void**)&h_f,  g_h_f);
    cudaGetSymbolAddress((void**)&h_b,  g_h_b);
    cudaGetSymbolAddress((void**)&yw,   g_yword);
    cudaGetSymbolAddress((void**)&yp,   g_ypool);
    cudaGetSymbolAddress((void**)&gw,   g_gw);
    cudaGetSymbolAddress((void**)&wraw, g_wraw);

    // 1. zero hidden states
    zero_h<<<(BATCH * HID) / 256, 256>>>(h_f, h_b);

    // 2. input-gate preactivations, both directions in one launch (z=2)
    dim3 gi_grid(BT / 128, G3 / 128, 2);
    tgemm<<<gi_grid, 256>>>(emb, emb, EMBD, inds,
                            w_ih_f, w_ih_b, b_ih_f, b_ih_b, nullptr,
                            gi_f, gi_b, BT, G3, EMBD, 0);

    // 3. bidirectional GRU recurrence
    dim3 gh_grid(BATCH / 128, G3 / 128, 2);
    for (int t = 0; t < TT; t++) {
        tgemm<<<gh_grid, 256>>>(h_f, h_b, HID, nullptr,
                                w_hh_f, w_hh_b, b_hh_f, b_hh_b, nullptr,
                                gh_f, gh_b, BATCH, G3, HID, 0);
        gru_step<<<(2 * BATCH * HID) / 256, 256>>>(gi_f, gi_b, gh_f, gh_b,
                                                   h_f, h_b, yw, t);
    }

    // 4. masked max pool
    maxpool<<<(BATCH * DD) / 256, 256>>>(inds, yw, yp);

    // 5. gw = tanh(y_pool @ w_global^T + b_global) * w_common
    dim3 gw_grid(BATCH / 128, DD / 128, 1);
    tgemm<<<gw_grid, 256>>>(yp, yp, DD, nullptr,
                            w_global, w_global, b_global, b_global, w_common,
                            gw, gw, BATCH, DD, DD, 1);

    // 6. l_emb = tanh(y_word @ w_local^T + b_local) -> scratch (reuse gi_f)
    dim3 le_grid(BT / 128, DD / 128, 1);
    tgemm<<<le_grid, 256>>>(yw, yw, DD, nullptr,
                            w_local, w_local, b_local, b_local, nullptr,
                            gi_f, gi_f, BT, DD, DD, 2);

    // 7. attention logits
    attn_reduce<<<BT / 8, 256>>>(gi_f, gw, b_common, wraw);

    // 8. softmax over T + weighted sum
    softmax_out<<<BATCH, 256>>>(wraw, yw, out);
}

// round 4
// speedup vs baseline: 3.5759x; 1.1670x over previous
#include <cuda_runtime.h>
#include <math.h>
#include <stdint.h>

#define BATCH 4096
#define TT    15
#define EMBD  300
#define HID   512
#define G3    1536
#define DD    1024
#define BT    (BATCH*TT)
#define VOCAB 12000

#define SROW      36                 // smem row stride in floats (32 + 4 pad)
#define STAGE_U32 (128*SROW)         // one array (A or B), in uint32
#define SMEM_B    (2*2*STAGE_U32*4)  // 2 stages x (A+B) bytes = 73728

// ---------------- scratch -----------------------------------------------------
__device__ float g_git_f[(size_t)VOCAB * G3];   // per-vocab gi table fwd (incl bias)
__device__ float g_git_b[(size_t)VOCAB * G3];
__device__ float g_gh_f[BATCH * G3];
__device__ float g_gh_b[BATCH * G3];
__device__ float g_h_f [BATCH * HID];
__device__ float g_h_b [BATCH * HID];
__device__ float g_yword[(size_t)BT * DD];
__device__ float g_ypool[BATCH * DD];
__device__ float g_gw  [BATCH * DD];
__device__ float g_wraw[BT];

// ---------------- TF32 helpers -------------------------------------------------
__device__ __forceinline__ uint32_t f2tf(float x) {
    uint32_t r; asm("cvt.rna.tf32.f32 %0, %1;" : "=r"(r) : "f"(x)); return r;
}
__device__ __forceinline__ void mma8(float* c,
    uint32_t a0, uint32_t a1, uint32_t a2, uint32_t a3,
    uint32_t b0, uint32_t b1)
{
    asm volatile(
        "mma.sync.aligned.m16n8k8.row.col.f32.tf32.tf32.f32 "
        "{%0,%1,%2,%3},{%4,%5,%6,%7},{%8,%9},{%0,%1,%2,%3};"
        : "+f"(c[0]), "+f"(c[1]), "+f"(c[2]), "+f"(c[3])
        : "r"(a0), "r"(a1), "r"(a2), "r"(a3), "r"(b0), "r"(b1));
}

// load one BK=32 chunk of A and B tiles into registers
__device__ __forceinline__ void stage_load(
    const float* const* aptr, const float* const* wptr,
    int k, int K, float4* ra, float4* rb)
{
    const float4 z4 = make_float4(0.f, 0.f, 0.f, 0.f);
    const bool v = (k < K);
    #pragma unroll
    for (int i = 0; i < 4; i++) {
        ra[i] = v ? *(const float4*)(aptr[i] + k) : z4;
        rb[i] = v ? *(const float4*)(wptr[i] + k) : z4;
    }
}

// store registers into a smem stage with permutation p(c)=(c%4)*8+c/4
__device__ __forceinline__ void stage_store(
    uint32_t* dst, int lr, int lc4, const float4* ra, const float4* rb)
{
    uint32_t* db = dst + STAGE_U32;
    #pragma unroll
    for (int i = 0; i < 4; i++) {
        const int base = (lr + i * 32) * SROW + lc4;
        dst[base +  0] = f2tf(ra[i].x);
        dst[base +  8] = f2tf(ra[i].y);
        dst[base + 16] = f2tf(ra[i].z);
        dst[base + 24] = f2tf(ra[i].w);
        db [base +  0] = f2tf(rb[i].x);
        db [base +  8] = f2tf(rb[i].y);
        db [base + 16] = f2tf(rb[i].z);
        db [base + 24] = f2tf(rb[i].w);
    }
}

// compute the 128x128 (per-CTA) tile contribution for one BK=32 chunk
__device__ __forceinline__ void mm_tile(
    const uint32_t* As, const uint32_t* Bs,
    int wm0, int wn0, int g, int q, float (*c)[8][4])
{
    const uint4* As4 = (const uint4*)As;
    const uint4* Bs4 = (const uint4*)Bs;
    #pragma unroll
    for (int h = 0; h < 2; h++) {
        const int fo = q * 2 + h;
        const uint4 aL0 = As4[(wm0 + g     ) * 9 + fo];
        const uint4 aH0 = As4[(wm0 + g +  8) * 9 + fo];
        const uint4 aL1 = As4[(wm0 + g + 16) * 9 + fo];
        const uint4 aH1 = As4[(wm0 + g + 24) * 9 + fo];
        uint4 bf[8];
        #pragma unroll
        for (int nt = 0; nt < 8; nt++)
            bf[nt] = Bs4[(wn0 + nt * 8 + g) * 9 + fo];
        #pragma unroll
        for (int s = 0; s < 2; s++) {
            const uint32_t A00 = s ? aL0.z : aL0.x;
            const uint32_t A20 = s ? aL0.w : aL0.y;
            const uint32_t A10 = s ? aH0.z : aH0.x;
            const uint32_t A30 = s ? aH0.w : aH0.y;
            const uint32_t A01 = s ? aL1.z : aL1.x;
            const uint32_t A21 = s ? aL1.w : aL1.y;
            const uint32_t A11 = s ? aH1.z : aH1.x;
            const uint32_t A31 = s ? aH1.w : aH1.y;
            #pragma unroll
            for (int nt = 0; nt < 8; nt++) {
                const uint32_t B0 = s ? bf[nt].z : bf[nt].x;
                const uint32_t B1 = s ? bf[nt].w : bf[nt].y;
                mma8(c[0][nt], A00, A10, A20, A30, B0, B1);
                mma8(c[1][nt], A01, A11, A21, A31, B0, B1);
            }
        }
    }
}

// ---------------- TF32 tensor-core NT GEMM (double-buffered) -------------------
// C[M,N] = A[M,K] @ W[N,K]^T + bias ; dual param sets via blockIdx.z
// epi: 0 = plain, 1 = tanh(.)*wc
__global__ void __launch_bounds__(256) tgemm(
    const float* __restrict__ A,  const float* __restrict__ A2, int lda,
    const float* __restrict__ W,  const float* __restrict__ W2,
    const float* __restrict__ bias, const float* __restrict__ bias2,
    const float* __restrict__ wc,
    float* __restrict__ C, float* __restrict__ C2,
    int M, int N, int K, int epi)
{
    if (blockIdx.z == 1) { A = A2; W = W2; bias = bias2; C = C2; }
    extern __shared__ uint32_t sm[];

    const int tid  = threadIdx.x;
    const int lane = tid & 31, wid = tid >> 5;
    const int g = lane >> 2, q = lane & 3;
    const int wm0 = (wid & 3) * 32;
    const int wn0 = (wid >> 2) * 64;
    const int row0 = blockIdx.x * 128;
    const int col0 = blockIdx.y * 128;
    const int lr  = tid >> 3;
    const int lc4 = tid & 7;

    const float* aptr[4];
    const float* wptr[4];
    #pragma unroll
    for (int i = 0; i < 4; i++) {
        int ar = row0 + lr + i * 32;
        if (ar >= M) ar = M - 1;                // clamp (stores guarded)
        aptr[i] = A + (long)ar * lda;
        wptr[i] = W + (long)(col0 + lr + i * 32) * K;
    }

    float c[2][8][4];
    #pragma unroll
    for (int mt = 0; mt < 2; mt++)
        #pragma unroll
        for (int nt = 0; nt < 8; nt++)
            #pragma unroll
            for (int j = 0; j < 4; j++) c[mt][nt][j] = 0.f;

    float4 ra[4], rb[4];
    const int nk = (K + 31) / 32;

    stage_load(aptr, wptr, lc4 * 4, K, ra, rb);
    stage_store(sm, lr, lc4, ra, rb);
    __syncthreads();

    for (int it = 0; it < nk; it++) {
        const bool more = (it + 1 < nk);
        if (more) stage_load(aptr, wptr, (it + 1) * 32 + lc4 * 4, K, ra, rb);
        const uint32_t* cur = sm + (it & 1) * (2 * STAGE_U32);
        mm_tile(cur, cur + STAGE_U32, wm0, wn0, g, q, c);
        if (more) {
            stage_store(sm + ((it + 1) & 1) * (2 * STAGE_U32), lr, lc4, ra, rb);
            __syncthreads();
        }
    }

    #pragma unroll
    for (int mt = 0; mt < 2; mt++) {
        const int r = row0 + wm0 + mt * 16 + g;
        #pragma unroll
        for (int nt = 0; nt < 8; nt++) {
            const int n = col0 + wn0 + nt * 8 + q * 2;
            const float b0 = bias[n], b1 = bias[n + 1];
            float v00 = c[mt][nt][0] + b0, v01 = c[mt][nt][1] + b1;
            float v10 = c[mt][nt][2] + b0, v11 = c[mt][nt][3] + b1;
            if (epi == 1) {
                const float w0 = wc[n], w1 = wc[n + 1];
                v00 = tanhf(v00) * w0; v01 = tanhf(v01) * w1;
                v10 = tanhf(v10) * w0; v11 = tanhf(v11) * w1;
            }
            if (r < M)
                *(float2*)(C + (long)r * N + n) = make_float2(v00, v01);
            if (r + 8 < M)
                *(float2*)(C + (long)(r + 8) * N + n) = make_float2(v10, v11);
        }
    }
}

// ---------------- fused attention logits ---------------------------------------
// wraw[r] = sum_n tanh( yw[r,:]@wl[n,:] + bl[n] ) * gw[r/TT, n] + bc
__global__ void __launch_bounds__(256) attn_w(
    const float* __restrict__ yw, const float* __restrict__ wl,
    const float* __restrict__ bl, const float* __restrict__ gw,
    const float* __restrict__ bc, float* __restrict__ wraw)
{
    extern __shared__ uint32_t sm[];
    __shared__ float red[128][9];

    const int tid  = threadIdx.x;
    const int lane = tid & 31, wid = tid >> 5;
    const int g = lane >> 2, q = lane & 3;
    const int wm0 = (wid & 3) * 32;
    const int wn0 = (wid >> 2) * 64;
    const int row0 = blockIdx.x * 128;
    const int lr  = tid >> 3;
    const int lc4 = tid & 7;

    const float* aptr[4];
    #pragma unroll
    for (int i = 0; i < 4; i++)
        aptr[i] = yw + (long)(row0 + lr + i * 32) * DD;

    int rb0[2], rb1[2];
    #pragma unroll
    for (int mt = 0; mt < 2; mt++) {
        const int r = row0 + wm0 + mt * 16 + g;
        rb0[mt] = r / TT;
        rb1[mt] = (r + 8) / TT;
    }
    float rowsum[2][2] = {{0.f, 0.f}, {0.f, 0.f}};

    float4 ra[4], rb[4];
    const int nk = DD / 32;   // 32

    for (int ct = 0; ct < DD / 128; ct++) {
        const int col0 = ct * 128;
        const float* wptr[4];
        #pragma unroll
        for (int i = 0; i < 4; i++)
            wptr[i] = wl + (long)(col0 + lr + i * 32) * DD;

        float c[2][8][4];
        #pragma unroll
        for (int mt = 0; mt < 2; mt++)
            #pragma unroll
            for (int nt = 0; nt < 8; nt++)
                #pragma unroll
                for (int j = 0; j < 4; j++) c[mt][nt][j] = 0.f;

        stage_load(aptr, wptr, lc4 * 4, DD, ra, rb);
        stage_store(sm, lr, lc4, ra, rb);
        __syncthreads();
        for (int it = 0; it < nk; it++) {
            const bool more = (it + 1 < nk);
            if (more) stage_load(aptr, wptr, (it + 1) * 32 + lc4 * 4, DD, ra, rb);
            const uint32_t* cur = sm + (it & 1) * (2 * STAGE_U32);
            mm_tile(cur, cur + STAGE_U32, wm0, wn0, g, q, c);
            if (more) {
                stage_store(sm + ((it + 1) & 1) * (2 * STAGE_U32), lr, lc4, ra, rb);
                __syncthreads();
            }
        }

        #pragma unroll
        for (int mt = 0; mt < 2; mt++) {
            #pragma unroll
            for (int nt = 0; nt < 8; nt++) {
                const int n = col0 + wn0 + nt * 8 + q * 2;
                const float bb0 = bl[n], bb1 = bl[n + 1];
                rowsum[mt][0] += tanhf(c[mt][nt][0] + bb0) * gw[(long)rb0[mt] * DD + n]
                               + tanhf(c[mt][nt][1] + bb1) * gw[(long)rb0[mt] * DD + n + 1];
                rowsum[mt][1] += tanhf(c[mt][nt][2] + bb0) * gw[(long)rb1[mt] * DD + n]
                               + tanhf(c[mt][nt][3] + bb1) * gw[(long)rb1[mt] * DD + n + 1];
            }
        }
        __syncthreads();
    }

    const int rc = (wid >> 2) * 4 + q;   // 0..7
    #pragma unroll
    for (int mt = 0; mt < 2; mt++) {
        red[wm0 + mt * 16 + g    ][rc] = rowsum[mt][0];
        red[wm0 + mt * 16 + g + 8][rc] = rowsum[mt][1];
    }
    __syncthreads();
    if (tid < 128) {
        float s = 0.f;
        #pragma unroll
        for (int x = 0; x < 8; x++) s += red[tid][x];
        wraw[row0 + tid] = s + bc[0];
    }
}

// ---------------- zero hidden states -------------------------------------------
__global__ void zero_h(float* __restrict__ h_f, float* __restrict__ h_b)
{
    const int i = blockIdx.x * 256 + threadIdx.x;
    h_f[i] = 0.f;
    h_b[i] = 0.f;
}

// ---------------- GRU gate update (gi gathered from vocab table) ---------------
__global__ void gru_step(const int* __restrict__ inds,
                         const float* __restrict__ git_f, const float* __restrict__ git_b,
                         const float* __restrict__ gh_f, const float* __restrict__ gh_b,
                         float* __restrict__ h_f, float* __restrict__ h_b,
                         float* __restrict__ y_word, int t)
{
    const int idx = blockIdx.x * 256 + threadIdx.x;
    const int dir = idx >= BATCH * HID;
    const int e   = dir ? idx - BATCH * HID : idx;
    const int b   = e >> 9;
    const int h   = e & (HID - 1);

    const float* git; const float* gh; float* hbuf; int tt; int off;
    if (!dir) { git = git_f; gh = gh_f; hbuf = h_f; tt = t;          off = 0;   }
    else      { git = git_b; gh = gh_b; hbuf = h_b; tt = TT - 1 - t; off = HID; }

    const int tok = inds[b * TT + tt];
    const float* gi = git + (long)tok * G3;
    const long ghb = (long)b * G3;
    const float hp = hbuf[e];
    const float ir = gi[h],         hr = gh[ghb + h];
    const float iz = gi[HID + h],   hz = gh[ghb + HID + h];
    const float in = gi[2*HID + h], hn = gh[ghb + 2*HID + h];
    const float r = 1.f / (1.f + expf(-(ir + hr)));
    const float z = 1.f / (1.f + expf(-(iz + hz)));
    const float n = tanhf(in + r * hn);
    const float hnew = (1.f - z) * n + z * hp;
    hbuf[e] = hnew;
    y_word[(long)(b * TT + tt) * DD + off + h] = hnew;
}

// ---------------- masked max pool ----------------------------------------------
__global__ void maxpool(const int* __restrict__ inds,
                        const float* __restrict__ y_word,
                        float* __restrict__ y_pool)
{
    const int idx = blockIdx.x * 256 + threadIdx.x;
    const int b = idx >> 10;
    const int d = idx & (DD - 1);
    float m = -INFINITY;
    #pragma unroll
    for (int t = 0; t < TT; t++) {
        if (inds[b * TT + t] != 0)
            m = fmaxf(m, y_word[(long)(b * TT + t) * DD + d]);
    }
    y_pool[idx] = m;
}

// ---------------- softmax over T + weighted sum -> output ----------------------
__global__ void softmax_out(const float* __restrict__ w_raw,
                            const float* __restrict__ y_word,
                            float* __restrict__ out)
{
    __shared__ float p[TT];
    const int b = blockIdx.x;
    if (threadIdx.x == 0) {
        float v[TT]; float mx = -INFINITY;
        #pragma unroll
        for (int t = 0; t < TT; t++) { v[t] = w_raw[b * TT + t]; mx = fmaxf(mx, v[t]); }
        float s = 0.f;
        #pragma unroll
        for (int t = 0; t < TT; t++) { v[t] = expf(v[t] - mx); s += v[t]; }
        const float inv = 1.f / s;
        #pragma unroll
        for (int t = 0; t < TT; t++) p[t] = v[t] * inv;
    }
    __syncthreads();
    for (int d = threadIdx.x; d < DD; d += 256) {
        float s = 0.f;
        #pragma unroll
        for (int t = 0; t < TT; t++)
            s += p[t] * y_word[((long)(b * TT + t)) * DD + d];
        out[(long)b * DD + d] = s;
    }
}

// ---------------- host launch --------------------------------------------------
extern "C" void kernel_launch(void* const* d_in, const int* in_sizes, int n_in,
                              void* d_out, int out_size)
{
    const int*   inds     = (const int*)  d_in[0];
    const float* emb      = (const float*)d_in[1];
    const float* w_ih_f   = (const float*)d_in[2];
    const float* w_hh_f   = (const float*)d_in[3];
    const float* b_ih_f   = (const float*)d_in[4];
    const float* b_hh_f   = (const float*)d_in[5];
    const float* w_ih_b   = (const float*)d_in[6];
    const float* w_hh_b   = (const float*)d_in[7];
    const float* b_ih_b   = (const float*)d_in[8];
    const float* b_hh_b   = (const float*)d_in[9];
    const float* w_local  = (const float*)d_in[10];
    const float* b_local  = (const float*)d_in[11];
    const float* w_global = (const float*)d_in[12];
    const float* b_global = (const float*)d_in[13];
    const float* w_common = (const float*)d_in[14];
    const float* b_common = (const float*)d_in[15];
    float* out = (float*)d_out;

    float *git_f, *git_b, *gh_f, *gh_b, *h_f, *h_b, *yw, *yp, *gw, *wraw;
    cudaGetSymbolAddress((void**)&git_f, g_git_f);
    cudaGetSymbolAddress((void**)&git_b, g_git_b);
    cudaGetSymbolAddress((void**)&gh_f, g_gh_f);
    cudaGetSymbolAddress((void**)&gh_b, g_gh_b);
    cudaGetSymbolAddress((void**)&h_f,  g_h_f);
    cudaGetSymbolAddress((void**)&h_b,  g_h_b);
    cudaGetSymbolAddress((void**)&yw,   g_yword);
    cudaGetSymbolAddress((void**)&yp,   g_ypool);
    cudaGetSymbolAddress((void**)&gw,   g_gw);
    cudaGetSymbolAddress((void**)&wraw, g_wraw);

    cudaFuncSetAttribute(tgemm,  cudaFuncAttributeMaxDynamicSharedMemorySize, SMEM_B);
    cudaFuncSetAttribute(attn_w, cudaFuncAttributeMaxDynamicSharedMemorySize, SMEM_B);

    // 1. zero hidden states
    zero_h<<<(BATCH * HID) / 256, 256>>>(h_f, h_b);

    // 2. per-vocab gi table: git = emb @ w_ih^T + b_ih   (both dirs, z=2)
    dim3 gt_grid((VOCAB + 127) / 128, G3 / 128, 2);
    tgemm<<<gt_grid, 256, SMEM_B>>>(emb, emb, EMBD,
                                    w_ih_f, w_ih_b, b_ih_f, b_ih_b, nullptr,
                                    git_f, git_b, VOCAB, G3, EMBD, 0);

    // 3. bidirectional GRU recurrence
    dim3 gh_grid(BATCH / 128, G3 / 128, 2);
    for (int t = 0; t < TT; t++) {
        tgemm<<<gh_grid, 256, SMEM_B>>>(h_f, h_b, HID,
                                        w_hh_f, w_hh_b, b_hh_f, b_hh_b, nullptr,
                                        gh_f, gh_b, BATCH, G3, HID, 0);
        gru_step<<<(2 * BATCH * HID) / 256, 256>>>(inds, git_f, git_b,
                                                   gh_f, gh_b, h_f, h_b, yw, t);
    }

    // 4. masked max pool
    maxpool<<<(BATCH * DD) / 256, 256>>>(inds, yw, yp);

    // 5. gw = tanh(y_pool @ w_global^T + b_global) * w_common
    dim3 gw_grid(BATCH / 128, DD / 128, 1);
    tgemm<<<gw_grid, 256, SMEM_B>>>(yp, yp, DD,
                                    w_global, w_global, b_global, b_global, w_common,
                                    gw, gw, BATCH, DD, DD, 1);

    // 6. fused l_emb -> tanh -> dot(gw) -> attention logits
    attn_w<<<BT / 128, 256, SMEM_B>>>(yw, w_local, b_local, gw, b_common, wraw);

    // 7. softmax over T + weighted sum
    softmax_out<<<BATCH, 256>>>(wraw, yw, out);
}